// round 12
// baseline (speedup 1.0000x reference)
#include <cuda_runtime.h>
#include <cuda_bf16.h>
#include <math.h>
#include <stdint.h>

#define BATCH 4
#define SEQ   4096
#define DIM   1024
#define HDIM  64

// bf16 hi/lo split Q,K,V (Q pre-scaled by 0.125*log2e). 2MB each.
__device__ __nv_bfloat16 g_Qh[(size_t)BATCH * SEQ * HDIM];
__device__ __nv_bfloat16 g_Ql[(size_t)BATCH * SEQ * HDIM];
__device__ __nv_bfloat16 g_Kh[(size_t)BATCH * SEQ * HDIM];
__device__ __nv_bfloat16 g_Kl[(size_t)BATCH * SEQ * HDIM];
__device__ __nv_bfloat16 g_Vh[(size_t)BATCH * SEQ * HDIM];
__device__ __nv_bfloat16 g_Vl[(size_t)BATCH * SEQ * HDIM];
// bf16 hi/lo split weights, [192][1024]
__device__ __nv_bfloat16 g_Wh[192 * DIM];
__device__ __nv_bfloat16 g_Wl[192 * DIM];

// ===================== helpers =====================
__device__ __forceinline__ uint32_t smem_u32(const void* p) {
    uint32_t a;
    asm("{ .reg .u64 t; cvta.to.shared.u64 t, %1; cvt.u32.u64 %0, t; }" : "=r"(a) : "l"(p));
    return a;
}
__device__ __forceinline__ float ex2(float x) {
    float y; asm("ex2.approx.f32 %0, %1;" : "=f"(y) : "f"(x)); return y;
}
__device__ __forceinline__ void cvt_pair(float a, float b, uint32_t& hi, uint32_t& lo) {
    __nv_bfloat16 ah = __float2bfloat16(a);
    __nv_bfloat16 bh = __float2bfloat16(b);
    float ar = a - __bfloat162float(ah);
    float br = b - __bfloat162float(bh);
    __nv_bfloat162 H = __halves2bfloat162(ah, bh);
    __nv_bfloat162 L = __halves2bfloat162(__float2bfloat16(ar), __float2bfloat16(br));
    hi = *reinterpret_cast<uint32_t*>(&H);
    lo = *reinterpret_cast<uint32_t*>(&L);
}

#define LDSM_X4(r0, r1, r2, r3, addr) \
    asm volatile("ldmatrix.sync.aligned.m8n8.x4.shared.b16 {%0,%1,%2,%3}, [%4];" \
        : "=r"(r0), "=r"(r1), "=r"(r2), "=r"(r3) : "r"(addr))
#define LDSM_X2(r0, r1, addr) \
    asm volatile("ldmatrix.sync.aligned.m8n8.x2.shared.b16 {%0,%1}, [%2];" \
        : "=r"(r0), "=r"(r1) : "r"(addr))
#define LDSM_X2_T(r0, r1, addr) \
    asm volatile("ldmatrix.sync.aligned.m8n8.x2.trans.shared.b16 {%0,%1}, [%2];" \
        : "=r"(r0), "=r"(r1) : "r"(addr))
#define MMA16816(d, a, b) \
    asm volatile("mma.sync.aligned.m16n8k16.row.col.f32.bf16.bf16.f32 " \
        "{%0,%1,%2,%3}, {%4,%5,%6,%7}, {%8,%9}, {%0,%1,%2,%3};" \
        : "+f"((d)[0]), "+f"((d)[1]), "+f"((d)[2]), "+f"((d)[3]) \
        : "r"((a)[0]), "r"((a)[1]), "r"((a)[2]), "r"((a)[3]), "r"((b)[0]), "r"((b)[1]))
#define CP16(dst, src) \
    asm volatile("cp.async.cg.shared.global [%0], [%1], 16;" :: "r"(dst), "l"(src) : "memory")
#define CP_COMMIT() asm volatile("cp.async.commit_group;" ::: "memory")
#define CP_WAIT0()  asm volatile("cp.async.wait_group 0;" ::: "memory")
#define CP_WAIT1()  asm volatile("cp.async.wait_group 1;" ::: "memory")

// ---------------------------------------------------------------------------
// Prepass: split weights into bf16 hi/lo. grid (64, 3), block 256.
// ---------------------------------------------------------------------------
__global__ void convert_w(const float* __restrict__ wq, const float* __restrict__ wk,
                          const float* __restrict__ wv)
{
    int mat = blockIdx.y;
    const float* src = (mat == 0) ? wq : (mat == 1) ? wk : wv;
    int idx = (blockIdx.x * 256 + threadIdx.x) * 4;
    float4 v = *(const float4*)(src + idx);
    uint32_t h0, l0, h1, l1;
    cvt_pair(v.x, v.y, h0, l0);
    cvt_pair(v.z, v.w, h1, l1);
    size_t o = (size_t)mat * (64 * DIM) + idx;
    *(uint32_t*)(g_Wh + o)     = h0;  *(uint32_t*)(g_Wh + o + 2) = h1;
    *(uint32_t*)(g_Wl + o)     = l0;  *(uint32_t*)(g_Wl + o + 2) = l1;
}

// ---------------------------------------------------------------------------
// QKV GEMM (unchanged from R10): fused N=192, M-tile 128, K-chunk 16, 2-stage.
// ---------------------------------------------------------------------------
#define QSTG 30720
#define QKV_SM (2 * QSTG)
__global__ __launch_bounds__(256, 1) void qkv_kernel(const float* __restrict__ x)
{
    extern __shared__ __align__(16) char smq[];

    const int tid = threadIdx.x;
    const int w = tid >> 5, l = tid & 31;
    const int m0 = blockIdx.x * 128;

    const float* xrow = x + (size_t)(m0 + (tid >> 1)) * DIM + (tid & 1) * 8;
    const uint32_t xdst = (uint32_t)(tid >> 1) * 48 + (uint32_t)(tid & 1) * 16;

    float acc[24][4];
    #pragma unroll
    for (int j = 0; j < 24; j++) { acc[j][0] = acc[j][1] = acc[j][2] = acc[j][3] = 0.0f; }

    {
        #pragma unroll
        for (int p = 0; p < 3; p++) {
            int wi = p * 256 + tid;
            int arr = (wi >= 384) ? 1 : 0;
            int i = wi - 384 * arr;
            int r = i >> 1, c = i & 1;
            const __nv_bfloat16* src = (arr ? g_Wl : g_Wh) + (size_t)r * DIM + c * 8;
            CP16(smem_u32(smq + 12288 + arr * 9216 + r * 48 + c * 16), src);
        }
        float4 xa = *(const float4*)(xrow);
        float4 xb = *(const float4*)(xrow + 4);
        uint32_t h[4], lo[4];
        cvt_pair(xa.x, xa.y, h[0], lo[0]);  cvt_pair(xa.z, xa.w, h[1], lo[1]);
        cvt_pair(xb.x, xb.y, h[2], lo[2]);  cvt_pair(xb.z, xb.w, h[3], lo[3]);
        *(uint4*)(smq + xdst)        = make_uint4(h[0], h[1], h[2], h[3]);
        *(uint4*)(smq + 6144 + xdst) = make_uint4(lo[0], lo[1], lo[2], lo[3]);
        CP_COMMIT();
    }

    for (int it = 0; it < DIM / 16; it++) {
        char* base = smq + (it & 1) * QSTG;
        char* nxt  = smq + ((it + 1) & 1) * QSTG;
        CP_WAIT0();
        __syncthreads();

        float4 xa, xb;
        const bool more = (it + 1 < DIM / 16);
        if (more) {
            const int k0n = (it + 1) * 16;
            #pragma unroll
            for (int p = 0; p < 3; p++) {
                int wi = p * 256 + tid;
                int arr = (wi >= 384) ? 1 : 0;
                int i = wi - 384 * arr;
                int r = i >> 1, c = i & 1;
                const __nv_bfloat16* src = (arr ? g_Wl : g_Wh) + (size_t)r * DIM + k0n + c * 8;
                CP16(smem_u32(nxt + 12288 + arr * 9216 + r * 48 + c * 16), src);
            }
            xa = *(const float4*)(xrow + k0n);
            xb = *(const float4*)(xrow + k0n + 4);
        }

        uint32_t ah[4], al[4];
        uint32_t arow = ((uint32_t)(16 * w + (l & 15)) * 24 + (uint32_t)((l >> 4) * 8)) * 2;
        LDSM_X4(ah[0], ah[1], ah[2], ah[3], smem_u32(base + arow));
        LDSM_X4(al[0], al[1], al[2], al[3], smem_u32(base + 6144 + arow));
        #pragma unroll
        for (int j = 0; j < 24; j++) {
            uint32_t brow = ((uint32_t)(8 * j + (l & 7)) * 24 + (uint32_t)(((l >> 3) & 1) * 8)) * 2;
            uint32_t bh[2], bl[2];
            LDSM_X2(bh[0], bh[1], smem_u32(base + 12288 + brow));
            LDSM_X2(bl[0], bl[1], smem_u32(base + 21504 + brow));
            MMA16816(acc[j], ah, bh);
            MMA16816(acc[j], ah, bl);
            MMA16816(acc[j], al, bh);
        }

        if (more) {
            uint32_t h[4], lo[4];
            cvt_pair(xa.x, xa.y, h[0], lo[0]);  cvt_pair(xa.z, xa.w, h[1], lo[1]);
            cvt_pair(xb.x, xb.y, h[2], lo[2]);  cvt_pair(xb.z, xb.w, h[3], lo[3]);
            *(uint4*)(nxt + xdst)        = make_uint4(h[0], h[1], h[2], h[3]);
            *(uint4*)(nxt + 6144 + xdst) = make_uint4(lo[0], lo[1], lo[2], lo[3]);
            CP_COMMIT();
        }
    }

    {
        const float QS = 0.125f * 1.4426950408889634f;
        __nv_bfloat16* const AH[3] = {g_Qh, g_Kh, g_Vh};
        __nv_bfloat16* const AL[3] = {g_Ql, g_Kl, g_Vl};
        int r0 = m0 + 16 * w + (l >> 2);
        int col2 = 2 * (l & 3);
        #pragma unroll
        for (int j = 0; j < 24; j++) {
            int mat = j >> 3;
            int col = 8 * (j & 7) + col2;
            float sc = (mat == 0) ? QS : 1.0f;
            uint32_t h, lo;
            cvt_pair(acc[j][0] * sc, acc[j][1] * sc, h, lo);
            *(uint32_t*)(AH[mat] + (size_t)r0 * HDIM + col) = h;
            *(uint32_t*)(AL[mat] + (size_t)r0 * HDIM + col) = lo;
            cvt_pair(acc[j][2] * sc, acc[j][3] * sc, h, lo);
            *(uint32_t*)(AH[mat] + (size_t)(r0 + 8) * HDIM + col) = h;
            *(uint32_t*)(AL[mat] + (size_t)(r0 + 8) * HDIM + col) = lo;
        }
    }
}

// ---------------------------------------------------------------------------
// FA2 attention, software-pipelined (ping-pong): iteration i issues S(i+1)
// MMAs alongside softmax(i)+PV(i) -> tensor pipe stays fed during softmax.
// 3 smem stages (rotating), 128 threads, q-tile 64, 2 CTAs/SM.
// grid = (SEQ/64, BATCH).
// ---------------------------------------------------------------------------
#define RSTR   144
#define STG_B  36864   // per stage: KH +0, KL +9216, VH +18432, VL +27648
#define ATTN_SM (3 * STG_B)   // 110592 -> 2 CTAs/SM (221184 <= 227KB)

__global__ __launch_bounds__(128, 2) void attn_kernel(float* __restrict__ out)
{
    extern __shared__ __align__(16) char sm[];

    const int tid = threadIdx.x;
    const int w = tid >> 5, l = tid & 31;
    const int b = blockIdx.y;
    const int q0 = blockIdx.x * 64;
    const size_t boff = (size_t)b * SEQ * HDIM;

    const __nv_bfloat16* Khp = g_Kh + boff;
    const __nv_bfloat16* Klp = g_Kl + boff;
    const __nv_bfloat16* Vhp = g_Vh + boff;
    const __nv_bfloat16* Vlp = g_Vl + boff;

    const char* p0 = sm;                // holds KV(i)   (V for PV)
    const char* p1 = sm + STG_B;        // holds KV(i+1) (K for next S)
    const char* p2 = sm + 2 * STG_B;    // prefetch target KV(i+2) (Q at start)

    // stage a KV tile -> given stage base (all 128 threads)
    auto stageKV = [&](const char* dst, int kt) {
        #pragma unroll
        for (int p = 0; p < 16; p++) {
            int arr = p >> 2;                     // 0=KH 1=KL 2=VH 3=VL
            int i = (p & 3) * 128 + tid;
            int r = i >> 3, c = i & 7;
            const __nv_bfloat16* src =
                (arr == 0) ? Khp : (arr == 1) ? Klp : (arr == 2) ? Vhp : Vlp;
            CP16(smem_u32(dst + arr * 9216 + r * RSTR + c * 16),
                 src + (size_t)(kt + r) * HDIM + c * 8);
        }
    };

    // ---- prologue: KV0 + Q (group 0), KV1 (group 1)
    stageKV(p0, 0);
    #pragma unroll
    for (int p = 0; p < 8; p++) {                 // arr: 0=Qh 1=Ql
        int arr = p >> 2;
        int i = (p & 3) * 128 + tid;
        int r = i >> 3, c = i & 7;
        const __nv_bfloat16* src = ((arr == 0) ? g_Qh : g_Ql) + boff;
        CP16(smem_u32(p2 + arr * 9216 + r * RSTR + c * 16),
             src + (size_t)(q0 + r) * HDIM + c * 8);
    }
    CP_COMMIT();
    stageKV(p1, 64);
    CP_COMMIT();

    CP_WAIT1();         // group0 (KV0 + Q) landed
    __syncthreads();

    // ---- Q fragments from p2
    uint32_t qh[4][4], ql[4][4];
    {
        uint32_t rowb = (uint32_t)(16 * w + (l & 15)) * RSTR + (uint32_t)(l >> 4) * 16;
        #pragma unroll
        for (int kk = 0; kk < 4; kk++) {
            LDSM_X4(qh[kk][0], qh[kk][1], qh[kk][2], qh[kk][3], smem_u32(p2 + rowb + kk * 32));
            LDSM_X4(ql[kk][0], ql[kk][1], ql[kk][2], ql[kk][3], smem_u32(p2 + 9216 + rowb + kk * 32));
        }
    }
    __syncthreads();    // Q reads done -> p2 reusable for KV(2)

    // S-MMA block (3-term) from a stage base
    auto computeS = [&](float sx[8][4], const char* base) {
        #pragma unroll
        for (int j = 0; j < 8; j++) {
            sx[j][0] = sx[j][1] = sx[j][2] = sx[j][3] = 0.0f;
            uint32_t rowb = (uint32_t)(8 * j + (l & 7)) * RSTR + (uint32_t)(((l >> 3) & 1) * 8) * 2;
            #pragma unroll
            for (int kk = 0; kk < 4; kk++) {
                uint32_t bh[2], bl[2];
                LDSM_X2(bh[0], bh[1], smem_u32(base + rowb + kk * 32));
                LDSM_X2(bl[0], bl[1], smem_u32(base + 9216 + rowb + kk * 32));
                MMA16816(sx[j], qh[kk], bh);
                MMA16816(sx[j], qh[kk], bl);
                MMA16816(sx[j], ql[kk], bh);
            }
        }
    };

    float o[8][4];
    #pragma unroll
    for (int j = 0; j < 8; j++) { o[j][0] = o[j][1] = o[j][2] = o[j][3] = 0.0f; }
    float m0r = -1e30f, m1r = -1e30f, l0r = 0.0f, l1r = 0.0f;

    float s_cur[8][4], s_nxt[8][4];
    computeS(s_cur, p0);   // S(0); KV0 resident

    for (int it = 0; it < SEQ / 64; it++) {
        CP_WAIT0();          // KV(it+1) landed
        __syncthreads();     // visible; stage p2 free (PV(it-1)/Q reads done)

        if (it + 2 < SEQ / 64) { stageKV(p2, (it + 2) * 64); CP_COMMIT(); }

        // ---- independent chain A: S(it+1) from p1 (tensor)
        if (it < SEQ / 64 - 1) computeS(s_nxt, p1);

        // ---- independent chain B: softmax(it) + PV(it) from p0
        float rm0 = m0r, rm1 = m1r;
        #pragma unroll
        for (int j = 0; j < 8; j++) {
            rm0 = fmaxf(rm0, fmaxf(s_cur[j][0], s_cur[j][1]));
            rm1 = fmaxf(rm1, fmaxf(s_cur[j][2], s_cur[j][3]));
        }
        rm0 = fmaxf(rm0, __shfl_xor_sync(0xffffffffu, rm0, 1));
        rm0 = fmaxf(rm0, __shfl_xor_sync(0xffffffffu, rm0, 2));
        rm1 = fmaxf(rm1, __shfl_xor_sync(0xffffffffu, rm1, 1));
        rm1 = fmaxf(rm1, __shfl_xor_sync(0xffffffffu, rm1, 2));
        float c0f = ex2(m0r - rm0), c1f = ex2(m1r - rm1);
        m0r = rm0;  m1r = rm1;
        float ls0 = 0.0f, ls1 = 0.0f;
        #pragma unroll
        for (int j = 0; j < 8; j++) {
            s_cur[j][0] = ex2(s_cur[j][0] - rm0);
            s_cur[j][1] = ex2(s_cur[j][1] - rm0);
            s_cur[j][2] = ex2(s_cur[j][2] - rm1);
            s_cur[j][3] = ex2(s_cur[j][3] - rm1);
            ls0 += s_cur[j][0] + s_cur[j][1];
            ls1 += s_cur[j][2] + s_cur[j][3];
            o[j][0] *= c0f;  o[j][1] *= c0f;
            o[j][2] *= c1f;  o[j][3] *= c1f;
        }
        ls0 += __shfl_xor_sync(0xffffffffu, ls0, 1);
        ls0 += __shfl_xor_sync(0xffffffffu, ls0, 2);
        ls1 += __shfl_xor_sync(0xffffffffu, ls1, 1);
        ls1 += __shfl_xor_sync(0xffffffffu, ls1, 2);
        l0r = l0r * c0f + ls0;
        l1r = l1r * c1f + ls1;

        #pragma unroll
        for (int kk = 0; kk < 4; kk++) {
            uint32_t ah[4], al[4];
            cvt_pair(s_cur[2 * kk][0],     s_cur[2 * kk][1],     ah[0], al[0]);
            cvt_pair(s_cur[2 * kk][2],     s_cur[2 * kk][3],     ah[1], al[1]);
            cvt_pair(s_cur[2 * kk + 1][0], s_cur[2 * kk + 1][1], ah[2], al[2]);
            cvt_pair(s_cur[2 * kk + 1][2], s_cur[2 * kk + 1][3], ah[3], al[3]);
            uint32_t vrow = (uint32_t)(16 * kk + (l & 7) + 8 * ((l >> 3) & 1)) * RSTR;
            #pragma unroll
            for (int j = 0; j < 8; j++) {
                uint32_t off = vrow + (uint32_t)j * 16;
                uint32_t vh[2], vl[2];
                LDSM_X2_T(vh[0], vh[1], smem_u32(p0 + 18432 + off));
                LDSM_X2_T(vl[0], vl[1], smem_u32(p0 + 27648 + off));
                MMA16816(o[j], ah, vh);
                MMA16816(o[j], ah, vl);
                MMA16816(o[j], al, vh);
            }
        }

        // rotate stages + promote s_nxt
        const char* t = p0; p0 = p1; p1 = p2; p2 = t;
        #pragma unroll
        for (int j = 0; j < 8; j++) {
            s_cur[j][0] = s_nxt[j][0];  s_cur[j][1] = s_nxt[j][1];
            s_cur[j][2] = s_nxt[j][2];  s_cur[j][3] = s_nxt[j][3];
        }
    }

    // ---- epilogue
    {
        float inv0 = 1.0f / l0r, inv1 = 1.0f / l1r;
        int r0 = q0 + 16 * w + (l >> 2);
        int col = 2 * (l & 3);
        float* op0 = out + ((size_t)b * SEQ + r0) * HDIM;
        float* op1 = op0 + 8 * HDIM;
        #pragma unroll
        for (int j = 0; j < 8; j++) {
            float2 v0 = {o[j][0] * inv0, o[j][1] * inv0};
            float2 v1 = {o[j][2] * inv1, o[j][3] * inv1};
            *(float2*)(op0 + 8 * j + col) = v0;
            *(float2*)(op1 + 8 * j + col) = v1;
        }
    }
}

// ---------------------------------------------------------------------------
extern "C" void kernel_launch(void* const* d_in, const int* in_sizes, int n_in,
                              void* d_out, int out_size)
{
    const float* x  = (const float*)d_in[0];
    const float* wq = (const float*)d_in[1];
    const float* wk = (const float*)d_in[2];
    const float* wv = (const float*)d_in[3];
    float* out = (float*)d_out;

    convert_w<<<dim3(64, 3), 256>>>(wq, wk, wv);

    cudaFuncSetAttribute(qkv_kernel, cudaFuncAttributeMaxDynamicSharedMemorySize, QKV_SM);
    qkv_kernel<<<(BATCH * SEQ) / 128, 256, QKV_SM>>>(x);

    cudaFuncSetAttribute(attn_kernel, cudaFuncAttributeMaxDynamicSharedMemorySize, ATTN_SM);
    attn_kernel<<<dim3(SEQ / 64, BATCH), 128, ATTN_SM>>>(out);
}

// round 13
// speedup vs baseline: 1.0163x; 1.0163x over previous
#include <cuda_runtime.h>
#include <cuda_bf16.h>
#include <math.h>
#include <stdint.h>

#define BATCH 4
#define SEQ   4096
#define DIM   1024
#define HDIM  64

// bf16 hi/lo split Q,K,V (Q pre-scaled by 0.125*log2e). 2MB each.
__device__ __nv_bfloat16 g_Qh[(size_t)BATCH * SEQ * HDIM];
__device__ __nv_bfloat16 g_Ql[(size_t)BATCH * SEQ * HDIM];
__device__ __nv_bfloat16 g_Kh[(size_t)BATCH * SEQ * HDIM];
__device__ __nv_bfloat16 g_Kl[(size_t)BATCH * SEQ * HDIM];
__device__ __nv_bfloat16 g_Vh[(size_t)BATCH * SEQ * HDIM];
__device__ __nv_bfloat16 g_Vl[(size_t)BATCH * SEQ * HDIM];
// bf16 hi/lo split weights, [192][1024]
__device__ __nv_bfloat16 g_Wh[192 * DIM];
__device__ __nv_bfloat16 g_Wl[192 * DIM];

// ===================== helpers =====================
__device__ __forceinline__ uint32_t smem_u32(const void* p) {
    uint32_t a;
    asm("{ .reg .u64 t; cvta.to.shared.u64 t, %1; cvt.u32.u64 %0, t; }" : "=r"(a) : "l"(p));
    return a;
}
__device__ __forceinline__ float ex2(float x) {
    float y; asm("ex2.approx.f32 %0, %1;" : "=f"(y) : "f"(x)); return y;
}
__device__ __forceinline__ void cvt_pair(float a, float b, uint32_t& hi, uint32_t& lo) {
    __nv_bfloat16 ah = __float2bfloat16(a);
    __nv_bfloat16 bh = __float2bfloat16(b);
    float ar = a - __bfloat162float(ah);
    float br = b - __bfloat162float(bh);
    __nv_bfloat162 H = __halves2bfloat162(ah, bh);
    __nv_bfloat162 L = __halves2bfloat162(__float2bfloat16(ar), __float2bfloat16(br));
    hi = *reinterpret_cast<uint32_t*>(&H);
    lo = *reinterpret_cast<uint32_t*>(&L);
}

#define LDSM_X4(r0, r1, r2, r3, addr) \
    asm volatile("ldmatrix.sync.aligned.m8n8.x4.shared.b16 {%0,%1,%2,%3}, [%4];" \
        : "=r"(r0), "=r"(r1), "=r"(r2), "=r"(r3) : "r"(addr))
#define LDSM_X4_T(r0, r1, r2, r3, addr) \
    asm volatile("ldmatrix.sync.aligned.m8n8.x4.trans.shared.b16 {%0,%1,%2,%3}, [%4];" \
        : "=r"(r0), "=r"(r1), "=r"(r2), "=r"(r3) : "r"(addr))
#define MMA16816(d, a, b) \
    asm volatile("mma.sync.aligned.m16n8k16.row.col.f32.bf16.bf16.f32 " \
        "{%0,%1,%2,%3}, {%4,%5,%6,%7}, {%8,%9}, {%0,%1,%2,%3};" \
        : "+f"((d)[0]), "+f"((d)[1]), "+f"((d)[2]), "+f"((d)[3]) \
        : "r"((a)[0]), "r"((a)[1]), "r"((a)[2]), "r"((a)[3]), "r"((b)[0]), "r"((b)[1]))
#define CP16(dst, src) \
    asm volatile("cp.async.cg.shared.global [%0], [%1], 16;" :: "r"(dst), "l"(src) : "memory")
#define CP_COMMIT() asm volatile("cp.async.commit_group;" ::: "memory")
#define CP_WAIT0()  asm volatile("cp.async.wait_group 0;" ::: "memory")

// ---------------------------------------------------------------------------
// Prepass: split weights into bf16 hi/lo. grid (64, 3), block 256.
// ---------------------------------------------------------------------------
__global__ void convert_w(const float* __restrict__ wq, const float* __restrict__ wk,
                          const float* __restrict__ wv)
{
    int mat = blockIdx.y;
    const float* src = (mat == 0) ? wq : (mat == 1) ? wk : wv;
    int idx = (blockIdx.x * 256 + threadIdx.x) * 4;
    float4 v = *(const float4*)(src + idx);
    uint32_t h0, l0, h1, l1;
    cvt_pair(v.x, v.y, h0, l0);
    cvt_pair(v.z, v.w, h1, l1);
    size_t o = (size_t)mat * (64 * DIM) + idx;
    *(uint32_t*)(g_Wh + o)     = h0;  *(uint32_t*)(g_Wh + o + 2) = h1;
    *(uint32_t*)(g_Wl + o)     = l0;  *(uint32_t*)(g_Wl + o + 2) = l1;
}

// ---------------------------------------------------------------------------
// QKV GEMM: fused N=192, M-tile 128, K-chunk 16, 2-stage; X4 B-loads.
// ---------------------------------------------------------------------------
#define QSTG 30720
#define QKV_SM (2 * QSTG)
__global__ __launch_bounds__(256, 1) void qkv_kernel(const float* __restrict__ x)
{
    extern __shared__ __align__(16) char smq[];

    const int tid = threadIdx.x;
    const int w = tid >> 5, l = tid & 31;
    const int m0 = blockIdx.x * 128;

    const float* xrow = x + (size_t)(m0 + (tid >> 1)) * DIM + (tid & 1) * 8;
    const uint32_t xdst = (uint32_t)(tid >> 1) * 48 + (uint32_t)(tid & 1) * 16;

    float acc[24][4];
    #pragma unroll
    for (int j = 0; j < 24; j++) { acc[j][0] = acc[j][1] = acc[j][2] = acc[j][3] = 0.0f; }

    {
        #pragma unroll
        for (int p = 0; p < 3; p++) {
            int wi = p * 256 + tid;
            int arr = (wi >= 384) ? 1 : 0;
            int i = wi - 384 * arr;
            int r = i >> 1, c = i & 1;
            const __nv_bfloat16* src = (arr ? g_Wl : g_Wh) + (size_t)r * DIM + c * 8;
            CP16(smem_u32(smq + 12288 + arr * 9216 + r * 48 + c * 16), src);
        }
        float4 xa = *(const float4*)(xrow);
        float4 xb = *(const float4*)(xrow + 4);
        uint32_t h[4], lo[4];
        cvt_pair(xa.x, xa.y, h[0], lo[0]);  cvt_pair(xa.z, xa.w, h[1], lo[1]);
        cvt_pair(xb.x, xb.y, h[2], lo[2]);  cvt_pair(xb.z, xb.w, h[3], lo[3]);
        *(uint4*)(smq + xdst)        = make_uint4(h[0], h[1], h[2], h[3]);
        *(uint4*)(smq + 6144 + xdst) = make_uint4(lo[0], lo[1], lo[2], lo[3]);
        CP_COMMIT();
    }

    // B-fragment X4 row: lanes 0-15 -> tile 2j (k halves), lanes 16-31 -> tile 2j+1
    const uint32_t bq = ((uint32_t)((l & 7) + 8 * (l >> 4)) * 24 + (uint32_t)(((l >> 3) & 1) * 8)) * 2;

    for (int it = 0; it < DIM / 16; it++) {
        char* base = smq + (it & 1) * QSTG;
        char* nxt  = smq + ((it + 1) & 1) * QSTG;
        CP_WAIT0();
        __syncthreads();

        float4 xa, xb;
        const bool more = (it + 1 < DIM / 16);
        if (more) {
            const int k0n = (it + 1) * 16;
            #pragma unroll
            for (int p = 0; p < 3; p++) {
                int wi = p * 256 + tid;
                int arr = (wi >= 384) ? 1 : 0;
                int i = wi - 384 * arr;
                int r = i >> 1, c = i & 1;
                const __nv_bfloat16* src = (arr ? g_Wl : g_Wh) + (size_t)r * DIM + k0n + c * 8;
                CP16(smem_u32(nxt + 12288 + arr * 9216 + r * 48 + c * 16), src);
            }
            xa = *(const float4*)(xrow + k0n);
            xb = *(const float4*)(xrow + k0n + 4);
        }

        uint32_t ah[4], al[4];
        uint32_t arow = ((uint32_t)(16 * w + (l & 15)) * 24 + (uint32_t)((l >> 4) * 8)) * 2;
        LDSM_X4(ah[0], ah[1], ah[2], ah[3], smem_u32(base + arow));
        LDSM_X4(al[0], al[1], al[2], al[3], smem_u32(base + 6144 + arow));
        #pragma unroll
        for (int jp = 0; jp < 12; jp++) {           // j pair = (2jp, 2jp+1)
            uint32_t boff = (uint32_t)(16 * jp) * 48 + bq;
            uint32_t bh[4], bl[4];
            LDSM_X4(bh[0], bh[1], bh[2], bh[3], smem_u32(base + 12288 + boff));
            LDSM_X4(bl[0], bl[1], bl[2], bl[3], smem_u32(base + 21504 + boff));
            MMA16816(acc[2 * jp],     ah, (bh));
            MMA16816(acc[2 * jp],     ah, (bl));
            MMA16816(acc[2 * jp],     al, (bh));
            MMA16816(acc[2 * jp + 1], ah, (bh + 2));
            MMA16816(acc[2 * jp + 1], ah, (bl + 2));
            MMA16816(acc[2 * jp + 1], al, (bh + 2));
        }

        if (more) {
            uint32_t h[4], lo[4];
            cvt_pair(xa.x, xa.y, h[0], lo[0]);  cvt_pair(xa.z, xa.w, h[1], lo[1]);
            cvt_pair(xb.x, xb.y, h[2], lo[2]);  cvt_pair(xb.z, xb.w, h[3], lo[3]);
            *(uint4*)(nxt + xdst)        = make_uint4(h[0], h[1], h[2], h[3]);
            *(uint4*)(nxt + 6144 + xdst) = make_uint4(lo[0], lo[1], lo[2], lo[3]);
            CP_COMMIT();
        }
    }

    {
        const float QS = 0.125f * 1.4426950408889634f;
        __nv_bfloat16* const AH[3] = {g_Qh, g_Kh, g_Vh};
        __nv_bfloat16* const AL[3] = {g_Ql, g_Kl, g_Vl};
        int r0 = m0 + 16 * w + (l >> 2);
        int col2 = 2 * (l & 3);
        #pragma unroll
        for (int j = 0; j < 24; j++) {
            int mat = j >> 3;
            int col = 8 * (j & 7) + col2;
            float sc = (mat == 0) ? QS : 1.0f;
            uint32_t h, lo;
            cvt_pair(acc[j][0] * sc, acc[j][1] * sc, h, lo);
            *(uint32_t*)(AH[mat] + (size_t)r0 * HDIM + col) = h;
            *(uint32_t*)(AL[mat] + (size_t)r0 * HDIM + col) = lo;
            cvt_pair(acc[j][2] * sc, acc[j][3] * sc, h, lo);
            *(uint32_t*)(AH[mat] + (size_t)(r0 + 8) * HDIM + col) = h;
            *(uint32_t*)(AL[mat] + (size_t)(r0 + 8) * HDIM + col) = lo;
        }
    }
}

// ---------------------------------------------------------------------------
// FA2 attention (R10 base): 128 threads, q-tile 64, KV tile 64, 2 CTAs/SM,
// 2-stage cp.async; X4-merged ldmatrix for K and V (half the LDSM count).
// grid = (SEQ/64, BATCH).
// ---------------------------------------------------------------------------
#define RSTR   144
#define STG_B  36864   // per stage: KH +0, KL +9216, VH +18432, VL +27648
#define ATTN_SM (2 * STG_B)   // 73728 -> 2 CTAs/SM

__global__ __launch_bounds__(128, 2) void attn_kernel(float* __restrict__ out)
{
    extern __shared__ __align__(16) char sm[];

    const int tid = threadIdx.x;
    const int w = tid >> 5, l = tid & 31;
    const int b = blockIdx.y;
    const int q0 = blockIdx.x * 64;
    const size_t boff = (size_t)b * SEQ * HDIM;

    const __nv_bfloat16* Khp = g_Kh + boff;
    const __nv_bfloat16* Klp = g_Kl + boff;
    const __nv_bfloat16* Vhp = g_Vh + boff;
    const __nv_bfloat16* Vlp = g_Vl + boff;

    // ---- prologue: KV tile 0 -> stage0, Q tile -> stage1
    #pragma unroll
    for (int p = 0; p < 16; p++) {
        int arr = p >> 2;
        int i = (p & 3) * 128 + tid;
        int r = i >> 3, c = i & 7;
        const __nv_bfloat16* src =
            (arr == 0) ? Khp : (arr == 1) ? Klp : (arr == 2) ? Vhp : Vlp;
        CP16(smem_u32(sm + arr * 9216 + r * RSTR + c * 16), src + (size_t)r * HDIM + c * 8);
    }
    CP_COMMIT();
    #pragma unroll
    for (int p = 0; p < 8; p++) {
        int arr = p >> 2;
        int i = (p & 3) * 128 + tid;
        int r = i >> 3, c = i & 7;
        const __nv_bfloat16* src = ((arr == 0) ? g_Qh : g_Ql) + boff;
        CP16(smem_u32(sm + STG_B + arr * 9216 + r * RSTR + c * 16),
             src + (size_t)(q0 + r) * HDIM + c * 8);
    }
    CP_COMMIT();
    CP_WAIT0();
    __syncthreads();

    // ---- Q fragments
    uint32_t qh[4][4], ql[4][4];
    {
        uint32_t rowb = (uint32_t)(16 * w + (l & 15)) * RSTR + (uint32_t)(l >> 4) * 16;
        #pragma unroll
        for (int kk = 0; kk < 4; kk++) {
            LDSM_X4(qh[kk][0], qh[kk][1], qh[kk][2], qh[kk][3], smem_u32(sm + STG_B + rowb + kk * 32));
            LDSM_X4(ql[kk][0], ql[kk][1], ql[kk][2], ql[kk][3], smem_u32(sm + STG_B + 9216 + rowb + kk * 32));
        }
    }

    float o[8][4];
    #pragma unroll
    for (int j = 0; j < 8; j++) { o[j][0] = o[j][1] = o[j][2] = o[j][3] = 0.0f; }
    float m0r = -1e30f, m1r = -1e30f, l0r = 0.0f, l1r = 0.0f;

    // K X4 row: lanes 0-15 -> key tile 2jp (k halves), 16-31 -> tile 2jp+1
    const uint32_t kq = ((uint32_t)((l & 7) + 8 * (l >> 4)) * RSTR) + (uint32_t)(((l >> 3) & 1) * 8) * 2;
    // V X4_T row: lanes 0-15 -> hd tile 2jp, 16-31 -> 2jp+1
    const uint32_t vq = (uint32_t)((l & 7) + 8 * ((l >> 3) & 1)) * RSTR + (uint32_t)(l >> 4) * 16;

    for (int it = 0; it < SEQ / 64; it++) {
        const char* base = sm + (it & 1) * STG_B;

        CP_WAIT0();
        __syncthreads();

        if (it + 1 < SEQ / 64) {
            const int ktn = (it + 1) * 64;
            char* nb = sm + ((it + 1) & 1) * STG_B;
            #pragma unroll
            for (int p = 0; p < 16; p++) {
                int arr = p >> 2;
                int i = (p & 3) * 128 + tid;
                int r = i >> 3, c = i & 7;
                const __nv_bfloat16* src =
                    (arr == 0) ? Khp : (arr == 1) ? Klp : (arr == 2) ? Vhp : Vlp;
                CP16(smem_u32(nb + arr * 9216 + r * RSTR + c * 16),
                     src + (size_t)(ktn + r) * HDIM + c * 8);
            }
            CP_COMMIT();
        }

        // ---- S = Q @ K^T (3-term, X4 K loads covering two j tiles)
        float s[8][4];
        #pragma unroll
        for (int j = 0; j < 8; j++) { s[j][0] = s[j][1] = s[j][2] = s[j][3] = 0.0f; }
        #pragma unroll
        for (int jp = 0; jp < 4; jp++) {
            #pragma unroll
            for (int kk = 0; kk < 4; kk++) {
                uint32_t boff = (uint32_t)(16 * jp) * RSTR + kq + kk * 32;
                uint32_t bh[4], bl[4];
                LDSM_X4(bh[0], bh[1], bh[2], bh[3], smem_u32(base + boff));
                LDSM_X4(bl[0], bl[1], bl[2], bl[3], smem_u32(base + 9216 + boff));
                MMA16816(s[2 * jp],     qh[kk], (bh));
                MMA16816(s[2 * jp],     qh[kk], (bl));
                MMA16816(s[2 * jp],     ql[kk], (bh));
                MMA16816(s[2 * jp + 1], qh[kk], (bh + 2));
                MMA16816(s[2 * jp + 1], qh[kk], (bl + 2));
                MMA16816(s[2 * jp + 1], ql[kk], (bh + 2));
            }
        }

        // ---- online softmax (log2 domain)
        float rm0 = m0r, rm1 = m1r;
        #pragma unroll
        for (int j = 0; j < 8; j++) {
            rm0 = fmaxf(rm0, fmaxf(s[j][0], s[j][1]));
            rm1 = fmaxf(rm1, fmaxf(s[j][2], s[j][3]));
        }
        rm0 = fmaxf(rm0, __shfl_xor_sync(0xffffffffu, rm0, 1));
        rm0 = fmaxf(rm0, __shfl_xor_sync(0xffffffffu, rm0, 2));
        rm1 = fmaxf(rm1, __shfl_xor_sync(0xffffffffu, rm1, 1));
        rm1 = fmaxf(rm1, __shfl_xor_sync(0xffffffffu, rm1, 2));
        float c0f = ex2(m0r - rm0), c1f = ex2(m1r - rm1);
        m0r = rm0;  m1r = rm1;
        float ls0 = 0.0f, ls1 = 0.0f;
        #pragma unroll
        for (int j = 0; j < 8; j++) {
            s[j][0] = ex2(s[j][0] - rm0);
            s[j][1] = ex2(s[j][1] - rm0);
            s[j][2] = ex2(s[j][2] - rm1);
            s[j][3] = ex2(s[j][3] - rm1);
            ls0 += s[j][0] + s[j][1];
            ls1 += s[j][2] + s[j][3];
            o[j][0] *= c0f;  o[j][1] *= c0f;
            o[j][2] *= c1f;  o[j][3] *= c1f;
        }
        ls0 += __shfl_xor_sync(0xffffffffu, ls0, 1);
        ls0 += __shfl_xor_sync(0xffffffffu, ls0, 2);
        ls1 += __shfl_xor_sync(0xffffffffu, ls1, 1);
        ls1 += __shfl_xor_sync(0xffffffffu, ls1, 2);
        l0r = l0r * c0f + ls0;
        l1r = l1r * c1f + ls1;

        // ---- O += P @ V (3-term; X4 trans V loads covering two hd tiles)
        #pragma unroll
        for (int kk = 0; kk < 4; kk++) {
            uint32_t ah[4], al[4];
            cvt_pair(s[2 * kk][0],     s[2 * kk][1],     ah[0], al[0]);
            cvt_pair(s[2 * kk][2],     s[2 * kk][3],     ah[1], al[1]);
            cvt_pair(s[2 * kk + 1][0], s[2 * kk + 1][1], ah[2], al[2]);
            cvt_pair(s[2 * kk + 1][2], s[2 * kk + 1][3], ah[3], al[3]);
            uint32_t vrow = (uint32_t)(16 * kk) * RSTR + vq;
            #pragma unroll
            for (int jp = 0; jp < 4; jp++) {
                uint32_t off = vrow + (uint32_t)jp * 32;
                uint32_t vh[4], vl[4];
                LDSM_X4_T(vh[0], vh[1], vh[2], vh[3], smem_u32(base + 18432 + off));
                LDSM_X4_T(vl[0], vl[1], vl[2], vl[3], smem_u32(base + 27648 + off));
                MMA16816(o[2 * jp],     ah, (vh));
                MMA16816(o[2 * jp],     ah, (vl));
                MMA16816(o[2 * jp],     al, (vh));
                MMA16816(o[2 * jp + 1], ah, (vh + 2));
                MMA16816(o[2 * jp + 1], ah, (vl + 2));
                MMA16816(o[2 * jp + 1], al, (vh + 2));
            }
        }
    }

    // ---- epilogue
    {
        float inv0 = 1.0f / l0r, inv1 = 1.0f / l1r;
        int r0 = q0 + 16 * w + (l >> 2);
        int col = 2 * (l & 3);
        float* op0 = out + ((size_t)b * SEQ + r0) * HDIM;
        float* op1 = op0 + 8 * HDIM;
        #pragma unroll
        for (int j = 0; j < 8; j++) {
            float2 v0 = {o[j][0] * inv0, o[j][1] * inv0};
            float2 v1 = {o[j][2] * inv1, o[j][3] * inv1};
            *(float2*)(op0 + 8 * j + col) = v0;
            *(float2*)(op1 + 8 * j + col) = v1;
        }
    }
}

// ---------------------------------------------------------------------------
extern "C" void kernel_launch(void* const* d_in, const int* in_sizes, int n_in,
                              void* d_out, int out_size)
{
    const float* x  = (const float*)d_in[0];
    const float* wq = (const float*)d_in[1];
    const float* wk = (const float*)d_in[2];
    const float* wv = (const float*)d_in[3];
    float* out = (float*)d_out;

    convert_w<<<dim3(64, 3), 256>>>(wq, wk, wv);

    cudaFuncSetAttribute(qkv_kernel, cudaFuncAttributeMaxDynamicSharedMemorySize, QKV_SM);
    qkv_kernel<<<(BATCH * SEQ) / 128, 256, QKV_SM>>>(x);

    cudaFuncSetAttribute(attn_kernel, cudaFuncAttributeMaxDynamicSharedMemorySize, ATTN_SM);
    attn_kernel<<<dim3(SEQ / 64, BATCH), 128, ATTN_SM>>>(out);
}

// round 14
// speedup vs baseline: 1.0959x; 1.0783x over previous
#include <cuda_runtime.h>
#include <cuda_bf16.h>
#include <math.h>
#include <stdint.h>

#define BATCH 4
#define SEQ   4096
#define DIM   1024
#define HDIM  64

// bf16 hi/lo split Q,K,V (Q pre-scaled by 0.125*log2e). 2MB each.
__device__ __nv_bfloat16 g_Qh[(size_t)BATCH * SEQ * HDIM];
__device__ __nv_bfloat16 g_Ql[(size_t)BATCH * SEQ * HDIM];
__device__ __nv_bfloat16 g_Kh[(size_t)BATCH * SEQ * HDIM];
__device__ __nv_bfloat16 g_Kl[(size_t)BATCH * SEQ * HDIM];
__device__ __nv_bfloat16 g_Vh[(size_t)BATCH * SEQ * HDIM];
__device__ __nv_bfloat16 g_Vl[(size_t)BATCH * SEQ * HDIM];
// bf16 hi/lo split weights, [192][1024]
__device__ __nv_bfloat16 g_Wh[192 * DIM];
__device__ __nv_bfloat16 g_Wl[192 * DIM];
// split-KV partials
__device__ float g_po[2 * (size_t)BATCH * SEQ * HDIM];   // unnormalized O halves
__device__ float g_pm[2 * BATCH * SEQ];                  // row max (log2 domain)
__device__ float g_pl[2 * BATCH * SEQ];                  // row sum

// ===================== helpers =====================
__device__ __forceinline__ uint32_t smem_u32(const void* p) {
    uint32_t a;
    asm("{ .reg .u64 t; cvta.to.shared.u64 t, %1; cvt.u32.u64 %0, t; }" : "=r"(a) : "l"(p));
    return a;
}
__device__ __forceinline__ float ex2(float x) {
    float y; asm("ex2.approx.f32 %0, %1;" : "=f"(y) : "f"(x)); return y;
}
__device__ __forceinline__ void cvt_pair(float a, float b, uint32_t& hi, uint32_t& lo) {
    __nv_bfloat16 ah = __float2bfloat16(a);
    __nv_bfloat16 bh = __float2bfloat16(b);
    float ar = a - __bfloat162float(ah);
    float br = b - __bfloat162float(bh);
    __nv_bfloat162 H = __halves2bfloat162(ah, bh);
    __nv_bfloat162 L = __halves2bfloat162(__float2bfloat16(ar), __float2bfloat16(br));
    hi = *reinterpret_cast<uint32_t*>(&H);
    lo = *reinterpret_cast<uint32_t*>(&L);
}
// cheap truncation split: hi = exact top-16 bits, lo = bf16(residual) (err ~2^-18)
__device__ __forceinline__ void pack_trunc(float a, float b, uint32_t& hi, uint32_t& lo) {
    uint32_t au = __float_as_uint(a), bu = __float_as_uint(b);
    hi = __byte_perm(au, bu, 0x7632);
    float ar = a - __uint_as_float(au & 0xFFFF0000u);
    float br = b - __uint_as_float(bu & 0xFFFF0000u);
    lo = __byte_perm(__float_as_uint(ar), __float_as_uint(br), 0x7632);
}

#define LDSM_X4(r0, r1, r2, r3, addr) \
    asm volatile("ldmatrix.sync.aligned.m8n8.x4.shared.b16 {%0,%1,%2,%3}, [%4];" \
        : "=r"(r0), "=r"(r1), "=r"(r2), "=r"(r3) : "r"(addr))
#define LDSM_X4_T(r0, r1, r2, r3, addr) \
    asm volatile("ldmatrix.sync.aligned.m8n8.x4.trans.shared.b16 {%0,%1,%2,%3}, [%4];" \
        : "=r"(r0), "=r"(r1), "=r"(r2), "=r"(r3) : "r"(addr))
#define MMA16816(d, a, b) \
    asm volatile("mma.sync.aligned.m16n8k16.row.col.f32.bf16.bf16.f32 " \
        "{%0,%1,%2,%3}, {%4,%5,%6,%7}, {%8,%9}, {%0,%1,%2,%3};" \
        : "+f"((d)[0]), "+f"((d)[1]), "+f"((d)[2]), "+f"((d)[3]) \
        : "r"((a)[0]), "r"((a)[1]), "r"((a)[2]), "r"((a)[3]), "r"((b)[0]), "r"((b)[1]))
#define CP16(dst, src) \
    asm volatile("cp.async.cg.shared.global [%0], [%1], 16;" :: "r"(dst), "l"(src) : "memory")
#define CP_COMMIT() asm volatile("cp.async.commit_group;" ::: "memory")
#define CP_WAIT0()  asm volatile("cp.async.wait_group 0;" ::: "memory")

// ---------------------------------------------------------------------------
// Prepass: split weights into bf16 hi/lo. grid (64, 3), block 256.
// ---------------------------------------------------------------------------
__global__ void convert_w(const float* __restrict__ wq, const float* __restrict__ wk,
                          const float* __restrict__ wv)
{
    int mat = blockIdx.y;
    const float* src = (mat == 0) ? wq : (mat == 1) ? wk : wv;
    int idx = (blockIdx.x * 256 + threadIdx.x) * 4;
    float4 v = *(const float4*)(src + idx);
    uint32_t h0, l0, h1, l1;
    cvt_pair(v.x, v.y, h0, l0);
    cvt_pair(v.z, v.w, h1, l1);
    size_t o = (size_t)mat * (64 * DIM) + idx;
    *(uint32_t*)(g_Wh + o)     = h0;  *(uint32_t*)(g_Wh + o + 2) = h1;
    *(uint32_t*)(g_Wl + o)     = l0;  *(uint32_t*)(g_Wl + o + 2) = l1;
}

// ---------------------------------------------------------------------------
// QKV GEMM: fused N=192, M-tile 64, block 128, 2 CTAs/SM, grid 256.
// Stage: XH@0(3072) XL@3072 WH@6144(9216) WL@15360 -> 24576 B.
// ---------------------------------------------------------------------------
#define QSTG 24576
#define QKV_SM (2 * QSTG)
__global__ __launch_bounds__(128, 2) void qkv_kernel(const float* __restrict__ x)
{
    extern __shared__ __align__(16) char smq[];

    const int tid = threadIdx.x;
    const int w = tid >> 5, l = tid & 31;
    const int m0 = blockIdx.x * 64;

    const float* xrow = x + (size_t)(m0 + (tid >> 1)) * DIM + (tid & 1) * 8;
    const uint32_t xdst = (uint32_t)(tid >> 1) * 48 + (uint32_t)(tid & 1) * 16;

    float acc[24][4];
    #pragma unroll
    for (int j = 0; j < 24; j++) { acc[j][0] = acc[j][1] = acc[j][2] = acc[j][3] = 0.0f; }

    {
        #pragma unroll
        for (int p = 0; p < 6; p++) {
            int wi = p * 128 + tid;               // 0..767
            int arr = (wi >= 384) ? 1 : 0;
            int i = wi - 384 * arr;
            int r = i >> 1, c = i & 1;
            const __nv_bfloat16* src = (arr ? g_Wl : g_Wh) + (size_t)r * DIM + c * 8;
            CP16(smem_u32(smq + 6144 + arr * 9216 + r * 48 + c * 16), src);
        }
        float4 xa = *(const float4*)(xrow);
        float4 xb = *(const float4*)(xrow + 4);
        uint32_t h[4], lo[4];
        cvt_pair(xa.x, xa.y, h[0], lo[0]);  cvt_pair(xa.z, xa.w, h[1], lo[1]);
        cvt_pair(xb.x, xb.y, h[2], lo[2]);  cvt_pair(xb.z, xb.w, h[3], lo[3]);
        *(uint4*)(smq + xdst)        = make_uint4(h[0], h[1], h[2], h[3]);
        *(uint4*)(smq + 3072 + xdst) = make_uint4(lo[0], lo[1], lo[2], lo[3]);
        CP_COMMIT();
    }

    const uint32_t bq = ((uint32_t)((l & 7) + 8 * (l >> 4)) * 24 + (uint32_t)(((l >> 3) & 1) * 8)) * 2;

    for (int it = 0; it < DIM / 16; it++) {
        char* base = smq + (it & 1) * QSTG;
        char* nxt  = smq + ((it + 1) & 1) * QSTG;
        CP_WAIT0();
        __syncthreads();

        float4 xa, xb;
        const bool more = (it + 1 < DIM / 16);
        if (more) {
            const int k0n = (it + 1) * 16;
            #pragma unroll
            for (int p = 0; p < 6; p++) {
                int wi = p * 128 + tid;
                int arr = (wi >= 384) ? 1 : 0;
                int i = wi - 384 * arr;
                int r = i >> 1, c = i & 1;
                const __nv_bfloat16* src = (arr ? g_Wl : g_Wh) + (size_t)r * DIM + k0n + c * 8;
                CP16(smem_u32(nxt + 6144 + arr * 9216 + r * 48 + c * 16), src);
            }
            xa = *(const float4*)(xrow + k0n);
            xb = *(const float4*)(xrow + k0n + 4);
        }

        uint32_t ah[4], al[4];
        uint32_t arow = ((uint32_t)(16 * w + (l & 15)) * 24 + (uint32_t)((l >> 4) * 8)) * 2;
        LDSM_X4(ah[0], ah[1], ah[2], ah[3], smem_u32(base + arow));
        LDSM_X4(al[0], al[1], al[2], al[3], smem_u32(base + 3072 + arow));
        #pragma unroll
        for (int jp = 0; jp < 12; jp++) {
            uint32_t boff = (uint32_t)(16 * jp) * 48 + bq;
            uint32_t bh[4], bl[4];
            LDSM_X4(bh[0], bh[1], bh[2], bh[3], smem_u32(base + 6144 + boff));
            LDSM_X4(bl[0], bl[1], bl[2], bl[3], smem_u32(base + 15360 + boff));
            MMA16816(acc[2 * jp],     ah, (bh));
            MMA16816(acc[2 * jp],     ah, (bl));
            MMA16816(acc[2 * jp],     al, (bh));
            MMA16816(acc[2 * jp + 1], ah, (bh + 2));
            MMA16816(acc[2 * jp + 1], ah, (bl + 2));
            MMA16816(acc[2 * jp + 1], al, (bh + 2));
        }

        if (more) {
            uint32_t h[4], lo[4];
            cvt_pair(xa.x, xa.y, h[0], lo[0]);  cvt_pair(xa.z, xa.w, h[1], lo[1]);
            cvt_pair(xb.x, xb.y, h[2], lo[2]);  cvt_pair(xb.z, xb.w, h[3], lo[3]);
            *(uint4*)(nxt + xdst)        = make_uint4(h[0], h[1], h[2], h[3]);
            *(uint4*)(nxt + 3072 + xdst) = make_uint4(lo[0], lo[1], lo[2], lo[3]);
            CP_COMMIT();
        }
    }

    {
        const float QS = 0.125f * 1.4426950408889634f;
        __nv_bfloat16* const AH[3] = {g_Qh, g_Kh, g_Vh};
        __nv_bfloat16* const AL[3] = {g_Ql, g_Kl, g_Vl};
        int r0 = m0 + 16 * w + (l >> 2);
        int col2 = 2 * (l & 3);
        #pragma unroll
        for (int j = 0; j < 24; j++) {
            int mat = j >> 3;
            int col = 8 * (j & 7) + col2;
            float sc = (mat == 0) ? QS : 1.0f;
            uint32_t h, lo;
            cvt_pair(acc[j][0] * sc, acc[j][1] * sc, h, lo);
            *(uint32_t*)(AH[mat] + (size_t)r0 * HDIM + col) = h;
            *(uint32_t*)(AL[mat] + (size_t)r0 * HDIM + col) = lo;
            cvt_pair(acc[j][2] * sc, acc[j][3] * sc, h, lo);
            *(uint32_t*)(AH[mat] + (size_t)(r0 + 8) * HDIM + col) = h;
            *(uint32_t*)(AL[mat] + (size_t)(r0 + 8) * HDIM + col) = lo;
        }
    }
}

// ---------------------------------------------------------------------------
// FA2 attention, split-KV (blockIdx.z halves), 3 CTAs/SM, 32 iters/CTA.
// Writes unnormalized partials; merge_kernel combines.
// grid = (SEQ/64, BATCH, 2).
// ---------------------------------------------------------------------------
#define RSTR   144
#define STG_B  36864
#define ATTN_SM (2 * STG_B)   // 73728; 3 CTAs/SM = 221184 <= 228KB

__global__ __launch_bounds__(128, 3) void attn_kernel()
{
    extern __shared__ __align__(16) char sm[];

    const int tid = threadIdx.x;
    const int w = tid >> 5, l = tid & 31;
    const int b = blockIdx.y;
    const int z = blockIdx.z;
    const int q0 = blockIdx.x * 64;
    const size_t boff = (size_t)b * SEQ * HDIM;
    const size_t kvoff = boff + (size_t)z * (SEQ / 2) * HDIM;

    const __nv_bfloat16* Khp = g_Kh + kvoff;
    const __nv_bfloat16* Klp = g_Kl + kvoff;
    const __nv_bfloat16* Vhp = g_Vh + kvoff;
    const __nv_bfloat16* Vlp = g_Vl + kvoff;

    // ---- prologue: KV tile 0 -> stage0, Q tile -> stage1
    #pragma unroll
    for (int p = 0; p < 16; p++) {
        int arr = p >> 2;
        int i = (p & 3) * 128 + tid;
        int r = i >> 3, c = i & 7;
        const __nv_bfloat16* src =
            (arr == 0) ? Khp : (arr == 1) ? Klp : (arr == 2) ? Vhp : Vlp;
        CP16(smem_u32(sm + arr * 9216 + r * RSTR + c * 16), src + (size_t)r * HDIM + c * 8);
    }
    CP_COMMIT();
    #pragma unroll
    for (int p = 0; p < 8; p++) {
        int arr = p >> 2;
        int i = (p & 3) * 128 + tid;
        int r = i >> 3, c = i & 7;
        const __nv_bfloat16* src = ((arr == 0) ? g_Qh : g_Ql) + boff;
        CP16(smem_u32(sm + STG_B + arr * 9216 + r * RSTR + c * 16),
             src + (size_t)(q0 + r) * HDIM + c * 8);
    }
    CP_COMMIT();
    CP_WAIT0();
    __syncthreads();

    uint32_t qh[4][4], ql[4][4];
    {
        uint32_t rowb = (uint32_t)(16 * w + (l & 15)) * RSTR + (uint32_t)(l >> 4) * 16;
        #pragma unroll
        for (int kk = 0; kk < 4; kk++) {
            LDSM_X4(qh[kk][0], qh[kk][1], qh[kk][2], qh[kk][3], smem_u32(sm + STG_B + rowb + kk * 32));
            LDSM_X4(ql[kk][0], ql[kk][1], ql[kk][2], ql[kk][3], smem_u32(sm + STG_B + 9216 + rowb + kk * 32));
        }
    }

    float o[8][4];
    #pragma unroll
    for (int j = 0; j < 8; j++) { o[j][0] = o[j][1] = o[j][2] = o[j][3] = 0.0f; }
    float m0r = -1e30f, m1r = -1e30f, l0r = 0.0f, l1r = 0.0f;

    const uint32_t kq = ((uint32_t)((l & 7) + 8 * (l >> 4)) * RSTR) + (uint32_t)(((l >> 3) & 1) * 8) * 2;
    const uint32_t vq = (uint32_t)((l & 7) + 8 * ((l >> 3) & 1)) * RSTR + (uint32_t)(l >> 4) * 16;

    const int NIT = SEQ / 2 / 64;   // 32
    for (int it = 0; it < NIT; it++) {
        const char* base = sm + (it & 1) * STG_B;

        CP_WAIT0();
        __syncthreads();

        if (it + 1 < NIT) {
            const int ktn = (it + 1) * 64;
            char* nb = sm + ((it + 1) & 1) * STG_B;
            #pragma unroll
            for (int p = 0; p < 16; p++) {
                int arr = p >> 2;
                int i = (p & 3) * 128 + tid;
                int r = i >> 3, c = i & 7;
                const __nv_bfloat16* src =
                    (arr == 0) ? Khp : (arr == 1) ? Klp : (arr == 2) ? Vhp : Vlp;
                CP16(smem_u32(nb + arr * 9216 + r * RSTR + c * 16),
                     src + (size_t)(ktn + r) * HDIM + c * 8);
            }
            CP_COMMIT();
        }

        // ---- S = Q @ K^T (3-term, X4 loads)
        float s[8][4];
        #pragma unroll
        for (int j = 0; j < 8; j++) { s[j][0] = s[j][1] = s[j][2] = s[j][3] = 0.0f; }
        #pragma unroll
        for (int jp = 0; jp < 4; jp++) {
            #pragma unroll
            for (int kk = 0; kk < 4; kk++) {
                uint32_t boff2 = (uint32_t)(16 * jp) * RSTR + kq + kk * 32;
                uint32_t bh[4], bl[4];
                LDSM_X4(bh[0], bh[1], bh[2], bh[3], smem_u32(base + boff2));
                LDSM_X4(bl[0], bl[1], bl[2], bl[3], smem_u32(base + 9216 + boff2));
                MMA16816(s[2 * jp],     qh[kk], (bh));
                MMA16816(s[2 * jp],     qh[kk], (bl));
                MMA16816(s[2 * jp],     ql[kk], (bh));
                MMA16816(s[2 * jp + 1], qh[kk], (bh + 2));
                MMA16816(s[2 * jp + 1], qh[kk], (bl + 2));
                MMA16816(s[2 * jp + 1], ql[kk], (bh + 2));
            }
        }

        // ---- online softmax (log2 domain)
        float rm0 = m0r, rm1 = m1r;
        #pragma unroll
        for (int j = 0; j < 8; j++) {
            rm0 = fmaxf(rm0, fmaxf(s[j][0], s[j][1]));
            rm1 = fmaxf(rm1, fmaxf(s[j][2], s[j][3]));
        }
        rm0 = fmaxf(rm0, __shfl_xor_sync(0xffffffffu, rm0, 1));
        rm0 = fmaxf(rm0, __shfl_xor_sync(0xffffffffu, rm0, 2));
        rm1 = fmaxf(rm1, __shfl_xor_sync(0xffffffffu, rm1, 1));
        rm1 = fmaxf(rm1, __shfl_xor_sync(0xffffffffu, rm1, 2));
        float c0f = ex2(m0r - rm0), c1f = ex2(m1r - rm1);
        m0r = rm0;  m1r = rm1;
        float ls0 = 0.0f, ls1 = 0.0f;
        #pragma unroll
        for (int j = 0; j < 8; j++) {
            s[j][0] = ex2(s[j][0] - rm0);
            s[j][1] = ex2(s[j][1] - rm0);
            s[j][2] = ex2(s[j][2] - rm1);
            s[j][3] = ex2(s[j][3] - rm1);
            ls0 += s[j][0] + s[j][1];
            ls1 += s[j][2] + s[j][3];
            o[j][0] *= c0f;  o[j][1] *= c0f;
            o[j][2] *= c1f;  o[j][3] *= c1f;
        }
        ls0 += __shfl_xor_sync(0xffffffffu, ls0, 1);
        ls0 += __shfl_xor_sync(0xffffffffu, ls0, 2);
        ls1 += __shfl_xor_sync(0xffffffffu, ls1, 1);
        ls1 += __shfl_xor_sync(0xffffffffu, ls1, 2);
        l0r = l0r * c0f + ls0;
        l1r = l1r * c1f + ls1;

        // ---- O += P @ V (3-term; truncation P-split, X4 trans V loads)
        #pragma unroll
        for (int kk = 0; kk < 4; kk++) {
            uint32_t ah[4], al[4];
            pack_trunc(s[2 * kk][0],     s[2 * kk][1],     ah[0], al[0]);
            pack_trunc(s[2 * kk][2],     s[2 * kk][3],     ah[1], al[1]);
            pack_trunc(s[2 * kk + 1][0], s[2 * kk + 1][1], ah[2], al[2]);
            pack_trunc(s[2 * kk + 1][2], s[2 * kk + 1][3], ah[3], al[3]);
            uint32_t vrow = (uint32_t)(16 * kk) * RSTR + vq;
            #pragma unroll
            for (int jp = 0; jp < 4; jp++) {
                uint32_t off = vrow + (uint32_t)jp * 32;
                uint32_t vh[4], vl[4];
                LDSM_X4_T(vh[0], vh[1], vh[2], vh[3], smem_u32(base + 18432 + off));
                LDSM_X4_T(vl[0], vl[1], vl[2], vl[3], smem_u32(base + 27648 + off));
                MMA16816(o[2 * jp],     ah, (vh));
                MMA16816(o[2 * jp],     ah, (vl));
                MMA16816(o[2 * jp],     al, (vh));
                MMA16816(o[2 * jp + 1], ah, (vh + 2));
                MMA16816(o[2 * jp + 1], ah, (vl + 2));
                MMA16816(o[2 * jp + 1], al, (vh + 2));
            }
        }
    }

    // ---- epilogue: write unnormalized partials + (m, l)
    {
        int r0 = q0 + 16 * w + (l >> 2);
        int col = 2 * (l & 3);
        float* op0 = g_po + (size_t)z * BATCH * SEQ * HDIM + ((size_t)b * SEQ + r0) * HDIM;
        float* op1 = op0 + 8 * HDIM;
        #pragma unroll
        for (int j = 0; j < 8; j++) {
            float2 v0 = {o[j][0], o[j][1]};
            float2 v1 = {o[j][2], o[j][3]};
            *(float2*)(op0 + 8 * j + col) = v0;
            *(float2*)(op1 + 8 * j + col) = v1;
        }
        if ((l & 3) == 0) {
            int ridx = z * BATCH * SEQ + b * SEQ + r0;
            g_pm[ridx] = m0r;       g_pl[ridx] = l0r;
            g_pm[ridx + 8] = m1r;   g_pl[ridx + 8] = l1r;
        }
    }
}

// ---------------------------------------------------------------------------
// Merge the two KV halves. grid 1024 x 256 threads; thread = 4 output floats.
// ---------------------------------------------------------------------------
__global__ void merge_kernel(float* __restrict__ out)
{
    int gid = blockIdx.x * 256 + threadIdx.x;
    int row = gid >> 4;
    int c4 = (gid & 15) * 4;
    float m0 = g_pm[row], m1 = g_pm[BATCH * SEQ + row];
    float M = fmaxf(m0, m1);
    float f0 = ex2(m0 - M), f1 = ex2(m1 - M);
    float lsum = g_pl[row] * f0 + g_pl[BATCH * SEQ + row] * f1;
    float inv = 1.0f / lsum;
    f0 *= inv;  f1 *= inv;
    float4 a0 = *(const float4*)(g_po + (size_t)row * HDIM + c4);
    float4 a1 = *(const float4*)(g_po + (size_t)BATCH * SEQ * HDIM + (size_t)row * HDIM + c4);
    float4 r;
    r.x = a0.x * f0 + a1.x * f1;
    r.y = a0.y * f0 + a1.y * f1;
    r.z = a0.z * f0 + a1.z * f1;
    r.w = a0.w * f0 + a1.w * f1;
    *(float4*)(out + (size_t)row * HDIM + c4) = r;
}

// ---------------------------------------------------------------------------
extern "C" void kernel_launch(void* const* d_in, const int* in_sizes, int n_in,
                              void* d_out, int out_size)
{
    const float* x  = (const float*)d_in[0];
    const float* wq = (const float*)d_in[1];
    const float* wk = (const float*)d_in[2];
    const float* wv = (const float*)d_in[3];
    float* out = (float*)d_out;

    convert_w<<<dim3(64, 3), 256>>>(wq, wk, wv);

    cudaFuncSetAttribute(qkv_kernel, cudaFuncAttributeMaxDynamicSharedMemorySize, QKV_SM);
    qkv_kernel<<<(BATCH * SEQ) / 64, 128, QKV_SM>>>(x);

    cudaFuncSetAttribute(attn_kernel, cudaFuncAttributeMaxDynamicSharedMemorySize, ATTN_SM);
    attn_kernel<<<dim3(SEQ / 64, BATCH, 2), 128, ATTN_SM>>>();

    merge_kernel<<<(BATCH * SEQ * HDIM) / (4 * 256), 256>>>(out);
}

// round 16
// speedup vs baseline: 1.1290x; 1.0303x over previous
#include <cuda_runtime.h>
#include <cuda_bf16.h>
#include <math.h>
#include <stdint.h>

#define BATCH 4
#define SEQ   4096
#define DIM   1024
#define HDIM  64

// bf16 hi/lo split Q,K,V (Q pre-scaled by 0.125*log2e). 2MB each.
__device__ __nv_bfloat16 g_Qh[(size_t)BATCH * SEQ * HDIM];
__device__ __nv_bfloat16 g_Ql[(size_t)BATCH * SEQ * HDIM];
__device__ __nv_bfloat16 g_Kh[(size_t)BATCH * SEQ * HDIM];
__device__ __nv_bfloat16 g_Kl[(size_t)BATCH * SEQ * HDIM];
__device__ __nv_bfloat16 g_Vh[(size_t)BATCH * SEQ * HDIM];
__device__ __nv_bfloat16 g_Vl[(size_t)BATCH * SEQ * HDIM];
// bf16 hi/lo split weights, [192][1024]
__device__ __nv_bfloat16 g_Wh[192 * DIM];
__device__ __nv_bfloat16 g_Wl[192 * DIM];
// split-KV partials (3 thirds)
__device__ float g_po[3 * (size_t)BATCH * SEQ * HDIM];
__device__ float g_pm[3 * BATCH * SEQ];
__device__ float g_pl[3 * BATCH * SEQ];

// ===================== helpers =====================
__device__ __forceinline__ uint32_t smem_u32(const void* p) {
    uint32_t a;
    asm("{ .reg .u64 t; cvta.to.shared.u64 t, %1; cvt.u32.u64 %0, t; }" : "=r"(a) : "l"(p));
    return a;
}
__device__ __forceinline__ float ex2(float x) {
    float y; asm("ex2.approx.f32 %0, %1;" : "=f"(y) : "f"(x)); return y;
}
__device__ __forceinline__ void cvt_pair(float a, float b, uint32_t& hi, uint32_t& lo) {
    __nv_bfloat16 ah = __float2bfloat16(a);
    __nv_bfloat16 bh = __float2bfloat16(b);
    float ar = a - __bfloat162float(ah);
    float br = b - __bfloat162float(bh);
    __nv_bfloat162 H = __halves2bfloat162(ah, bh);
    __nv_bfloat162 L = __halves2bfloat162(__float2bfloat16(ar), __float2bfloat16(br));
    hi = *reinterpret_cast<uint32_t*>(&H);
    lo = *reinterpret_cast<uint32_t*>(&L);
}
// cheap truncation split: hi = exact top-16 bits, lo = bf16(residual)
__device__ __forceinline__ void pack_trunc(float a, float b, uint32_t& hi, uint32_t& lo) {
    uint32_t au = __float_as_uint(a), bu = __float_as_uint(b);
    hi = __byte_perm(au, bu, 0x7632);
    float ar = a - __uint_as_float(au & 0xFFFF0000u);
    float br = b - __uint_as_float(bu & 0xFFFF0000u);
    lo = __byte_perm(__float_as_uint(ar), __float_as_uint(br), 0x7632);
}

#define LDSM_X4(r0, r1, r2, r3, addr) \
    asm volatile("ldmatrix.sync.aligned.m8n8.x4.shared.b16 {%0,%1,%2,%3}, [%4];" \
        : "=r"(r0), "=r"(r1), "=r"(r2), "=r"(r3) : "r"(addr))
#define LDSM_X4_T(r0, r1, r2, r3, addr) \
    asm volatile("ldmatrix.sync.aligned.m8n8.x4.trans.shared.b16 {%0,%1,%2,%3}, [%4];" \
        : "=r"(r0), "=r"(r1), "=r"(r2), "=r"(r3) : "r"(addr))
#define MMA16816(d, a, b) \
    asm volatile("mma.sync.aligned.m16n8k16.row.col.f32.bf16.bf16.f32 " \
        "{%0,%1,%2,%3}, {%4,%5,%6,%7}, {%8,%9}, {%0,%1,%2,%3};" \
        : "+f"((d)[0]), "+f"((d)[1]), "+f"((d)[2]), "+f"((d)[3]) \
        : "r"((a)[0]), "r"((a)[1]), "r"((a)[2]), "r"((a)[3]), "r"((b)[0]), "r"((b)[1]))
#define CP16(dst, src) \
    asm volatile("cp.async.cg.shared.global [%0], [%1], 16;" :: "r"(dst), "l"(src) : "memory")
#define CP_COMMIT() asm volatile("cp.async.commit_group;" ::: "memory")
#define CP_WAIT0()  asm volatile("cp.async.wait_group 0;" ::: "memory")

// ---------------------------------------------------------------------------
// Prepass: split weights into bf16 hi/lo. grid (64, 3), block 256.
// ---------------------------------------------------------------------------
__global__ void convert_w(const float* __restrict__ wq, const float* __restrict__ wk,
                          const float* __restrict__ wv)
{
    int mat = blockIdx.y;
    const float* src = (mat == 0) ? wq : (mat == 1) ? wk : wv;
    int idx = (blockIdx.x * 256 + threadIdx.x) * 4;
    float4 v = *(const float4*)(src + idx);
    uint32_t h0, l0, h1, l1;
    cvt_pair(v.x, v.y, h0, l0);
    cvt_pair(v.z, v.w, h1, l1);
    size_t o = (size_t)mat * (64 * DIM) + idx;
    *(uint32_t*)(g_Wh + o)     = h0;  *(uint32_t*)(g_Wh + o + 2) = h1;
    *(uint32_t*)(g_Wl + o)     = l0;  *(uint32_t*)(g_Wl + o + 2) = l1;
}

// ---------------------------------------------------------------------------
// QKV GEMM: fused N=192, M-tile 64, block 128, 2 CTAs/SM, grid 256.
// ---------------------------------------------------------------------------
#define QSTG 24576
#define QKV_SM (2 * QSTG)
__global__ __launch_bounds__(128, 2) void qkv_kernel(const float* __restrict__ x)
{
    extern __shared__ __align__(16) char smq[];

    const int tid = threadIdx.x;
    const int w = tid >> 5, l = tid & 31;
    const int m0 = blockIdx.x * 64;

    const float* xrow = x + (size_t)(m0 + (tid >> 1)) * DIM + (tid & 1) * 8;
    const uint32_t xdst = (uint32_t)(tid >> 1) * 48 + (uint32_t)(tid & 1) * 16;

    float acc[24][4];
    #pragma unroll
    for (int j = 0; j < 24; j++) { acc[j][0] = acc[j][1] = acc[j][2] = acc[j][3] = 0.0f; }

    {
        #pragma unroll
        for (int p = 0; p < 6; p++) {
            int wi = p * 128 + tid;
            int arr = (wi >= 384) ? 1 : 0;
            int i = wi - 384 * arr;
            int r = i >> 1, c = i & 1;
            const __nv_bfloat16* src = (arr ? g_Wl : g_Wh) + (size_t)r * DIM + c * 8;
            CP16(smem_u32(smq + 6144 + arr * 9216 + r * 48 + c * 16), src);
        }
        float4 xa = *(const float4*)(xrow);
        float4 xb = *(const float4*)(xrow + 4);
        uint32_t h[4], lo[4];
        cvt_pair(xa.x, xa.y, h[0], lo[0]);  cvt_pair(xa.z, xa.w, h[1], lo[1]);
        cvt_pair(xb.x, xb.y, h[2], lo[2]);  cvt_pair(xb.z, xb.w, h[3], lo[3]);
        *(uint4*)(smq + xdst)        = make_uint4(h[0], h[1], h[2], h[3]);
        *(uint4*)(smq + 3072 + xdst) = make_uint4(lo[0], lo[1], lo[2], lo[3]);
        CP_COMMIT();
    }

    const uint32_t bq = ((uint32_t)((l & 7) + 8 * (l >> 4)) * 24 + (uint32_t)(((l >> 3) & 1) * 8)) * 2;

    for (int it = 0; it < DIM / 16; it++) {
        char* base = smq + (it & 1) * QSTG;
        char* nxt  = smq + ((it + 1) & 1) * QSTG;
        CP_WAIT0();
        __syncthreads();

        float4 xa, xb;
        const bool more = (it + 1 < DIM / 16);
        if (more) {
            const int k0n = (it + 1) * 16;
            #pragma unroll
            for (int p = 0; p < 6; p++) {
                int wi = p * 128 + tid;
                int arr = (wi >= 384) ? 1 : 0;
                int i = wi - 384 * arr;
                int r = i >> 1, c = i & 1;
                const __nv_bfloat16* src = (arr ? g_Wl : g_Wh) + (size_t)r * DIM + k0n + c * 8;
                CP16(smem_u32(nxt + 6144 + arr * 9216 + r * 48 + c * 16), src);
            }
            xa = *(const float4*)(xrow + k0n);
            xb = *(const float4*)(xrow + k0n + 4);
        }

        uint32_t ah[4], al[4];
        uint32_t arow = ((uint32_t)(16 * w + (l & 15)) * 24 + (uint32_t)((l >> 4) * 8)) * 2;
        LDSM_X4(ah[0], ah[1], ah[2], ah[3], smem_u32(base + arow));
        LDSM_X4(al[0], al[1], al[2], al[3], smem_u32(base + 3072 + arow));
        #pragma unroll
        for (int jp = 0; jp < 12; jp++) {
            uint32_t boff = (uint32_t)(16 * jp) * 48 + bq;
            uint32_t bh[4], bl[4];
            LDSM_X4(bh[0], bh[1], bh[2], bh[3], smem_u32(base + 6144 + boff));
            LDSM_X4(bl[0], bl[1], bl[2], bl[3], smem_u32(base + 15360 + boff));
            MMA16816(acc[2 * jp],     ah, (bh));
            MMA16816(acc[2 * jp],     ah, (bl));
            MMA16816(acc[2 * jp],     al, (bh));
            MMA16816(acc[2 * jp + 1], ah, (bh + 2));
            MMA16816(acc[2 * jp + 1], ah, (bl + 2));
            MMA16816(acc[2 * jp + 1], al, (bh + 2));
        }

        if (more) {
            uint32_t h[4], lo[4];
            cvt_pair(xa.x, xa.y, h[0], lo[0]);  cvt_pair(xa.z, xa.w, h[1], lo[1]);
            cvt_pair(xb.x, xb.y, h[2], lo[2]);  cvt_pair(xb.z, xb.w, h[3], lo[3]);
            *(uint4*)(nxt + xdst)        = make_uint4(h[0], h[1], h[2], h[3]);
            *(uint4*)(nxt + 3072 + xdst) = make_uint4(lo[0], lo[1], lo[2], lo[3]);
            CP_COMMIT();
        }
    }

    {
        const float QS = 0.125f * 1.4426950408889634f;
        __nv_bfloat16* const AH[3] = {g_Qh, g_Kh, g_Vh};
        __nv_bfloat16* const AL[3] = {g_Ql, g_Kl, g_Vl};
        int r0 = m0 + 16 * w + (l >> 2);
        int col2 = 2 * (l & 3);
        #pragma unroll
        for (int j = 0; j < 24; j++) {
            int mat = j >> 3;
            int col = 8 * (j & 7) + col2;
            float sc = (mat == 0) ? QS : 1.0f;
            uint32_t h, lo;
            cvt_pair(acc[j][0] * sc, acc[j][1] * sc, h, lo);
            *(uint32_t*)(AH[mat] + (size_t)r0 * HDIM + col) = h;
            *(uint32_t*)(AL[mat] + (size_t)r0 * HDIM + col) = lo;
            cvt_pair(acc[j][2] * sc, acc[j][3] * sc, h, lo);
            *(uint32_t*)(AH[mat] + (size_t)(r0 + 8) * HDIM + col) = h;
            *(uint32_t*)(AL[mat] + (size_t)(r0 + 8) * HDIM + col) = lo;
        }
    }
}

// ---------------------------------------------------------------------------
// FA2 attention, split-KV in 3 (tiles 22/21/21), 3 CTAs/SM.
// grid = (SEQ/64, BATCH, 3) = 768 CTAs -> waves 444 + 324.
// ---------------------------------------------------------------------------
#define RSTR   144
#define STG_B  36864
#define ATTN_SM (2 * STG_B)

__global__ __launch_bounds__(128, 3) void attn_kernel(const float* __restrict__ unused)
{
    extern __shared__ __align__(16) char sm[];

    const int tid = threadIdx.x;
    const int w = tid >> 5, l = tid & 31;
    const int b = blockIdx.y;
    const int z = blockIdx.z;
    const int q0 = blockIdx.x * 64;
    const size_t boff = (size_t)b * SEQ * HDIM;

    const int t0  = (z == 0) ? 0 : ((z == 1) ? 22 : 43);   // first KV tile
    const int NIT = (z == 0) ? 22 : 21;
    const size_t kvoff = boff + (size_t)t0 * 64 * HDIM;

    const __nv_bfloat16* Khp = g_Kh + kvoff;
    const __nv_bfloat16* Klp = g_Kl + kvoff;
    const __nv_bfloat16* Vhp = g_Vh + kvoff;
    const __nv_bfloat16* Vlp = g_Vl + kvoff;

    // ---- prologue: KV tile 0 -> stage0, Q tile -> stage1
    #pragma unroll
    for (int p = 0; p < 16; p++) {
        int arr = p >> 2;
        int i = (p & 3) * 128 + tid;
        int r = i >> 3, c = i & 7;
        const __nv_bfloat16* src =
            (arr == 0) ? Khp : (arr == 1) ? Klp : (arr == 2) ? Vhp : Vlp;
        CP16(smem_u32(sm + arr * 9216 + r * RSTR + c * 16), src + (size_t)r * HDIM + c * 8);
    }
    CP_COMMIT();
    #pragma unroll
    for (int p = 0; p < 8; p++) {
        int arr = p >> 2;
        int i = (p & 3) * 128 + tid;
        int r = i >> 3, c = i & 7;
        const __nv_bfloat16* src = ((arr == 0) ? g_Qh : g_Ql) + boff;
        CP16(smem_u32(sm + STG_B + arr * 9216 + r * RSTR + c * 16),
             src + (size_t)(q0 + r) * HDIM + c * 8);
    }
    CP_COMMIT();
    CP_WAIT0();
    __syncthreads();

    uint32_t qh[4][4], ql[4][4];
    {
        uint32_t rowb = (uint32_t)(16 * w + (l & 15)) * RSTR + (uint32_t)(l >> 4) * 16;
        #pragma unroll
        for (int kk = 0; kk < 4; kk++) {
            LDSM_X4(qh[kk][0], qh[kk][1], qh[kk][2], qh[kk][3], smem_u32(sm + STG_B + rowb + kk * 32));
            LDSM_X4(ql[kk][0], ql[kk][1], ql[kk][2], ql[kk][3], smem_u32(sm + STG_B + 9216 + rowb + kk * 32));
        }
    }

    float o[8][4];
    #pragma unroll
    for (int j = 0; j < 8; j++) { o[j][0] = o[j][1] = o[j][2] = o[j][3] = 0.0f; }
    float m0r = -1e30f, m1r = -1e30f, l0r = 0.0f, l1r = 0.0f;

    const uint32_t kq = ((uint32_t)((l & 7) + 8 * (l >> 4)) * RSTR) + (uint32_t)(((l >> 3) & 1) * 8) * 2;
    const uint32_t vq = (uint32_t)((l & 7) + 8 * ((l >> 3) & 1)) * RSTR + (uint32_t)(l >> 4) * 16;

    for (int it = 0; it < NIT; it++) {
        const char* base = sm + (it & 1) * STG_B;

        CP_WAIT0();
        __syncthreads();

        if (it + 1 < NIT) {
            const int ktn = (it + 1) * 64;
            char* nb = sm + ((it + 1) & 1) * STG_B;
            #pragma unroll
            for (int p = 0; p < 16; p++) {
                int arr = p >> 2;
                int i = (p & 3) * 128 + tid;
                int r = i >> 3, c = i & 7;
                const __nv_bfloat16* src =
                    (arr == 0) ? Khp : (arr == 1) ? Klp : (arr == 2) ? Vhp : Vlp;
                CP16(smem_u32(nb + arr * 9216 + r * RSTR + c * 16),
                     src + (size_t)(ktn + r) * HDIM + c * 8);
            }
            CP_COMMIT();
        }

        // ---- S = Q @ K^T (3-term, X4 loads)
        float s[8][4];
        #pragma unroll
        for (int j = 0; j < 8; j++) { s[j][0] = s[j][1] = s[j][2] = s[j][3] = 0.0f; }
        #pragma unroll
        for (int jp = 0; jp < 4; jp++) {
            #pragma unroll
            for (int kk = 0; kk < 4; kk++) {
                uint32_t boff2 = (uint32_t)(16 * jp) * RSTR + kq + kk * 32;
                uint32_t bh[4], bl[4];
                LDSM_X4(bh[0], bh[1], bh[2], bh[3], smem_u32(base + boff2));
                LDSM_X4(bl[0], bl[1], bl[2], bl[3], smem_u32(base + 9216 + boff2));
                MMA16816(s[2 * jp],     qh[kk], (bh));
                MMA16816(s[2 * jp],     qh[kk], (bl));
                MMA16816(s[2 * jp],     ql[kk], (bh));
                MMA16816(s[2 * jp + 1], qh[kk], (bh + 2));
                MMA16816(s[2 * jp + 1], qh[kk], (bl + 2));
                MMA16816(s[2 * jp + 1], ql[kk], (bh + 2));
            }
        }

        // ---- online softmax (log2 domain)
        float rm0 = m0r, rm1 = m1r;
        #pragma unroll
        for (int j = 0; j < 8; j++) {
            rm0 = fmaxf(rm0, fmaxf(s[j][0], s[j][1]));
            rm1 = fmaxf(rm1, fmaxf(s[j][2], s[j][3]));
        }
        rm0 = fmaxf(rm0, __shfl_xor_sync(0xffffffffu, rm0, 1));
        rm0 = fmaxf(rm0, __shfl_xor_sync(0xffffffffu, rm0, 2));
        rm1 = fmaxf(rm1, __shfl_xor_sync(0xffffffffu, rm1, 1));
        rm1 = fmaxf(rm1, __shfl_xor_sync(0xffffffffu, rm1, 2));
        float c0f = ex2(m0r - rm0), c1f = ex2(m1r - rm1);
        m0r = rm0;  m1r = rm1;
        float ls0 = 0.0f, ls1 = 0.0f;
        #pragma unroll
        for (int j = 0; j < 8; j++) {
            s[j][0] = ex2(s[j][0] - rm0);
            s[j][1] = ex2(s[j][1] - rm0);
            s[j][2] = ex2(s[j][2] - rm1);
            s[j][3] = ex2(s[j][3] - rm1);
            ls0 += s[j][0] + s[j][1];
            ls1 += s[j][2] + s[j][3];
            o[j][0] *= c0f;  o[j][1] *= c0f;
            o[j][2] *= c1f;  o[j][3] *= c1f;
        }
        ls0 += __shfl_xor_sync(0xffffffffu, ls0, 1);
        ls0 += __shfl_xor_sync(0xffffffffu, ls0, 2);
        ls1 += __shfl_xor_sync(0xffffffffu, ls1, 1);
        ls1 += __shfl_xor_sync(0xffffffffu, ls1, 2);
        l0r = l0r * c0f + ls0;
        l1r = l1r * c1f + ls1;

        // ---- O += P @ V (3-term; truncation P-split, X4 trans V loads)
        #pragma unroll
        for (int kk = 0; kk < 4; kk++) {
            uint32_t ah[4], al[4];
            pack_trunc(s[2 * kk][0],     s[2 * kk][1],     ah[0], al[0]);
            pack_trunc(s[2 * kk][2],     s[2 * kk][3],     ah[1], al[1]);
            pack_trunc(s[2 * kk + 1][0], s[2 * kk + 1][1], ah[2], al[2]);
            pack_trunc(s[2 * kk + 1][2], s[2 * kk + 1][3], ah[3], al[3]);
            uint32_t vrow = (uint32_t)(16 * kk) * RSTR + vq;
            #pragma unroll
            for (int jp = 0; jp < 4; jp++) {
                uint32_t off = vrow + (uint32_t)jp * 32;
                uint32_t vh[4], vl[4];
                LDSM_X4_T(vh[0], vh[1], vh[2], vh[3], smem_u32(base + 18432 + off));
                LDSM_X4_T(vl[0], vl[1], vl[2], vl[3], smem_u32(base + 27648 + off));
                MMA16816(o[2 * jp],     ah, (vh));
                MMA16816(o[2 * jp],     ah, (vl));
                MMA16816(o[2 * jp],     al, (vh));
                MMA16816(o[2 * jp + 1], ah, (vh + 2));
                MMA16816(o[2 * jp + 1], ah, (vl + 2));
                MMA16816(o[2 * jp + 1], al, (vh + 2));
            }
        }
    }

    // ---- epilogue: unnormalized partials + (m, l) into slot z
    {
        int r0 = q0 + 16 * w + (l >> 2);
        int col = 2 * (l & 3);
        float* op0 = g_po + (size_t)z * BATCH * SEQ * HDIM + ((size_t)b * SEQ + r0) * HDIM;
        float* op1 = op0 + 8 * HDIM;
        #pragma unroll
        for (int j = 0; j < 8; j++) {
            float2 v0 = {o[j][0], o[j][1]};
            float2 v1 = {o[j][2], o[j][3]};
            *(float2*)(op0 + 8 * j + col) = v0;
            *(float2*)(op1 + 8 * j + col) = v1;
        }
        if ((l & 3) == 0) {
            int ridx = z * BATCH * SEQ + b * SEQ + r0;
            g_pm[ridx] = m0r;       g_pl[ridx] = l0r;
            g_pm[ridx + 8] = m1r;   g_pl[ridx + 8] = l1r;
        }
    }
}

// ---------------------------------------------------------------------------
// Merge 3 KV thirds. grid 1024 x 256; thread = 4 output floats.
// ---------------------------------------------------------------------------
__global__ void merge_kernel(float* __restrict__ out)
{
    int gid = blockIdx.x * 256 + threadIdx.x;
    int row = gid >> 4;
    int c4 = (gid & 15) * 4;
    float m0 = g_pm[row];
    float m1 = g_pm[BATCH * SEQ + row];
    float m2 = g_pm[2 * BATCH * SEQ + row];
    float M = fmaxf(m0, fmaxf(m1, m2));
    float f0 = ex2(m0 - M), f1 = ex2(m1 - M), f2 = ex2(m2 - M);
    float lsum = g_pl[row] * f0 + g_pl[BATCH * SEQ + row] * f1 + g_pl[2 * BATCH * SEQ + row] * f2;
    float inv = 1.0f / lsum;
    f0 *= inv;  f1 *= inv;  f2 *= inv;
    size_t ro = (size_t)row * HDIM + c4;
    float4 a0 = *(const float4*)(g_po + ro);
    float4 a1 = *(const float4*)(g_po + (size_t)BATCH * SEQ * HDIM + ro);
    float4 a2 = *(const float4*)(g_po + 2 * (size_t)BATCH * SEQ * HDIM + ro);
    float4 r;
    r.x = a0.x * f0 + a1.x * f1 + a2.x * f2;
    r.y = a0.y * f0 + a1.y * f1 + a2.y * f2;
    r.z = a0.z * f0 + a1.z * f1 + a2.z * f2;
    r.w = a0.w * f0 + a1.w * f1 + a2.w * f2;
    *(float4*)(out + ro) = r;
}

// ---------------------------------------------------------------------------
extern "C" void kernel_launch(void* const* d_in, const int* in_sizes, int n_in,
                              void* d_out, int out_size)
{
    const float* x  = (const float*)d_in[0];
    const float* wq = (const float*)d_in[1];
    const float* wk = (const float*)d_in[2];
    const float* wv = (const float*)d_in[3];
    float* out = (float*)d_out;

    convert_w<<<dim3(64, 3), 256>>>(wq, wk, wv);

    cudaFuncSetAttribute(qkv_kernel, cudaFuncAttributeMaxDynamicSharedMemorySize, QKV_SM);
    qkv_kernel<<<(BATCH * SEQ) / 64, 128, QKV_SM>>>(x);

    cudaFuncSetAttribute(attn_kernel, cudaFuncAttributeMaxDynamicSharedMemorySize, ATTN_SM);
    attn_kernel<<<dim3(SEQ / 64, BATCH, 3), 128, ATTN_SM>>>(x);

    merge_kernel<<<(BATCH * SEQ * HDIM) / (4 * 256), 256>>>(out);
}